// round 1
// baseline (speedup 1.0000x reference)
#include <cuda_runtime.h>
#include <cstdint>

#define BB 16384
#define TT 2048
#define HH 16

// Scratch: x transposed to [T, B] so the GRU kernel's per-step load is coalesced.
__device__ float g_xT[(size_t)BB * (size_t)TT];

typedef unsigned long long ull;

__device__ __forceinline__ ull pk2(float a, float b) {
    ull r; asm("mov.b64 %0, {%1, %2};" : "=l"(r) : "f"(a), "f"(b)); return r;
}
__device__ __forceinline__ void upk2(ull v, float& a, float& b) {
    asm("mov.b64 {%0, %1}, %2;" : "=f"(a), "=f"(b) : "l"(v));
}
__device__ __forceinline__ ull ffma2(ull a, ull b, ull c) {
    ull d; asm("fma.rn.f32x2 %0, %1, %2, %3;" : "=l"(d) : "l"(a), "l"(b), "l"(c)); return d;
}
__device__ __forceinline__ float ex2f(float x) {
    float y; asm("ex2.approx.f32 %0, %1;" : "=f"(y) : "f"(x)); return y;
}
__device__ __forceinline__ float rcpf(float x) {
    float y; asm("rcp.approx.f32 %0, %1;" : "=f"(y) : "f"(x)); return y;
}
// sigmoid(x) = 1 / (1 + 2^(-x*log2e))
__device__ __forceinline__ float sigmf(float x) {
    return rcpf(1.0f + ex2f(-1.4426950408889634f * x));
}
// tanh(x) = 1 - 2/(e^{2x}+1), e^{2x} = 2^(2x*log2e)
__device__ __forceinline__ float tanhf_fast(float x) {
    float e = ex2f(2.8853900817779268f * x);
    return fmaf(-2.0f, rcpf(e + 1.0f), 1.0f);
}

// ---------------------------------------------------------------------------
// Kernel 1: transpose x [B, T] -> g_xT [T, B]
// ---------------------------------------------------------------------------
__global__ void transpose_kernel(const float* __restrict__ x) {
    __shared__ float tile[32][33];
    int t0 = blockIdx.x * 32;
    int b0 = blockIdx.y * 32;
    int tx = threadIdx.x, ty = threadIdx.y;
#pragma unroll
    for (int i = 0; i < 4; i++) {
        tile[ty + i * 8][tx] = x[(size_t)(b0 + ty + i * 8) * TT + (t0 + tx)];
    }
    __syncthreads();
#pragma unroll
    for (int i = 0; i < 4; i++) {
        g_xT[(size_t)(t0 + ty + i * 8) * BB + (b0 + tx)] = tile[tx][ty + i * 8];
    }
}

// ---------------------------------------------------------------------------
// Kernel 2: GRU scan.
//   - A lane PAIR (even/odd lanes) handles 2 batch elements packed as f32x2.
//   - Each thread owns 8 hidden indices j (even lane: j=0..7, odd: j=8..15)
//     and computes gate rows {j, 16+j, 32+j} for both packed elements.
//   - w_hh lives in SMEM duplicated to f32x2, with k-order permuted per half
//     so both lanes execute identical code against hx[] = [own h | partner h].
//   - h exchanged between the pair each step via shfl_xor(1).
// ---------------------------------------------------------------------------

__device__ __forceinline__ ull dot16(const ull* __restrict__ wr, const ull hx[16], ull acc) {
#pragma unroll
    for (int k2 = 0; k2 < 8; k2++) {
        ulonglong2 w = ((const ulonglong2*)wr)[k2];
        acc = ffma2(w.x, hx[2 * k2], acc);
        acc = ffma2(w.y, hx[2 * k2 + 1], acc);
    }
    return acc;
}

__global__ __launch_bounds__(128, 1)
void gru_kernel(const float* __restrict__ w_ih, const float* __restrict__ w_hh,
                const float* __restrict__ b_ih, const float* __restrict__ b_hh,
                const float* __restrict__ w_fc, const float* __restrict__ b_fc,
                float* __restrict__ out)
{
    // w2p[half][r][kk]: r in [0,24): gate = r/8 (0=r,1=z,2=n), jj = r%8.
    // Row = gate*16 + half*8 + jj. kk<8 -> own h order, kk>=8 -> partner order.
    __shared__ ull w2p[2][24][16];

    int tid = threadIdx.x;
    for (int idx = tid; idx < 2 * 24 * 16; idx += 128) {
        int h    = idx / 384;
        int rem  = idx % 384;
        int r    = rem / 16;
        int kk   = rem % 16;
        int gate = r >> 3;
        int jj   = r & 7;
        int row  = gate * 16 + h * 8 + jj;
        int srck = (kk < 8) ? (h * 8 + kk) : ((h ^ 1) * 8 + (kk - 8));
        float v  = w_hh[row * 16 + srck];
        w2p[h][r][kk] = pk2(v, v);
    }
    __syncthreads();

    int g    = blockIdx.x * 128 + tid;
    int half = g & 1;
    int base = g & ~1;   // elements handled: base, base+1

    // Per-thread constants for its 8 absolute hidden indices j = half*8 + jj
    float wir[8], wiz[8], win[8], bsr[8], bsz[8], bin[8], bhn[8];
#pragma unroll
    for (int jj = 0; jj < 8; jj++) {
        int j   = half * 8 + jj;
        wir[jj] = __ldg(&w_ih[j]);
        wiz[jj] = __ldg(&w_ih[16 + j]);
        win[jj] = __ldg(&w_ih[32 + j]);
        bsr[jj] = __ldg(&b_ih[j])      + __ldg(&b_hh[j]);
        bsz[jj] = __ldg(&b_ih[16 + j]) + __ldg(&b_hh[16 + j]);
        bin[jj] = __ldg(&b_ih[32 + j]);
        bhn[jj] = __ldg(&b_hh[32 + j]);
    }
    const ull* wb = &w2p[half][0][0];

    // hx[0..7] = own h components, hx[8..15] = partner's (both as f32x2 over 2 elems)
    ull hx[16];
#pragma unroll
    for (int k = 0; k < 16; k++) hx[k] = 0ull;

    const float2* xp = ((const float2*)g_xT) + (base >> 1);
    float2 xv = __ldg(&xp[0]);

    for (int t = 0; t < TT; t++) {
        float x0 = xv.x, x1 = xv.y;
        int tn = (t < TT - 1) ? (t + 1) : t;
        float2 xnext = __ldg(&xp[(size_t)tn * (BB / 2)]);

        float r0a[8], r1a[8], z0a[8], z1a[8];

        // r gate (rows 0..7 of this half's table)
#pragma unroll
        for (int jj = 0; jj < 8; jj++) {
            ull acc = pk2(fmaf(x0, wir[jj], bsr[jj]), fmaf(x1, wir[jj], bsr[jj]));
            acc = dot16(wb + jj * 16, hx, acc);
            float a0, a1; upk2(acc, a0, a1);
            r0a[jj] = sigmf(a0);
            r1a[jj] = sigmf(a1);
        }
        // z gate (rows 8..15)
#pragma unroll
        for (int jj = 0; jj < 8; jj++) {
            ull acc = pk2(fmaf(x0, wiz[jj], bsz[jj]), fmaf(x1, wiz[jj], bsz[jj]));
            acc = dot16(wb + (8 + jj) * 16, hx, acc);
            float a0, a1; upk2(acc, a0, a1);
            z0a[jj] = sigmf(a0);
            z1a[jj] = sigmf(a1);
        }
        // n gate (rows 16..23) + deferred h update (old h must be used by all dots)
        ull hnew[8];
#pragma unroll
        for (int jj = 0; jj < 8; jj++) {
            ull acc = pk2(bhn[jj], bhn[jj]);          // gh_n accumulates b_hh_n
            acc = dot16(wb + (16 + jj) * 16, hx, acc);
            float gh0, gh1; upk2(acc, gh0, gh1);
            float pre0 = fmaf(r0a[jj], gh0, fmaf(x0, win[jj], bin[jj]));
            float pre1 = fmaf(r1a[jj], gh1, fmaf(x1, win[jj], bin[jj]));
            float n0 = tanhf_fast(pre0);
            float n1 = tanhf_fast(pre1);
            float h0, h1; upk2(hx[jj], h0, h1);
            h0 = fmaf(z0a[jj], h0 - n0, n0);          // (1-z)n + z h
            h1 = fmaf(z1a[jj], h1 - n1, n1);
            hnew[jj] = pk2(h0, h1);
        }
#pragma unroll
        for (int jj = 0; jj < 8; jj++) hx[jj] = hnew[jj];

        // exchange own h with pair partner -> hx[8..15]
#pragma unroll
        for (int jj = 0; jj < 8; jj++) {
            unsigned lo = (unsigned)hx[jj];
            unsigned hi = (unsigned)(hx[jj] >> 32);
            lo = __shfl_xor_sync(0xffffffffu, lo, 1);
            hi = __shfl_xor_sync(0xffffffffu, hi, 1);
            hx[8 + jj] = ((ull)hi << 32) | (ull)lo;
        }

        xv = xnext;
    }

    // FC epilogue: out[b] = sum_j h[b][j] * w_fc[j] + b_fc
    float p0 = 0.0f, p1 = 0.0f;
#pragma unroll
    for (int jj = 0; jj < 8; jj++) {
        float wf = __ldg(&w_fc[half * 8 + jj]);
        float h0, h1; upk2(hx[jj], h0, h1);
        p0 = fmaf(h0, wf, p0);
        p1 = fmaf(h1, wf, p1);
    }
    p0 += __shfl_xor_sync(0xffffffffu, p0, 1);
    p1 += __shfl_xor_sync(0xffffffffu, p1, 1);
    if (half == 0) {
        float bf = __ldg(b_fc);
        float2 o;
        o.x = p0 + bf;
        o.y = p1 + bf;
        *(float2*)(out + base) = o;
    }
}

// ---------------------------------------------------------------------------
extern "C" void kernel_launch(void* const* d_in, const int* in_sizes, int n_in,
                              void* d_out, int out_size)
{
    const float* x    = (const float*)d_in[0];
    const float* w_ih = (const float*)d_in[1];
    const float* w_hh = (const float*)d_in[2];
    const float* b_ih = (const float*)d_in[3];
    const float* b_hh = (const float*)d_in[4];
    const float* w_fc = (const float*)d_in[5];
    const float* b_fc = (const float*)d_in[6];
    float* out = (float*)d_out;

    dim3 tb(32, 8);
    dim3 tg(TT / 32, BB / 32);
    transpose_kernel<<<tg, tb>>>(x);

    gru_kernel<<<BB / 128 / 2 * 2 / 128 * 128 ? 128 : 128, 128>>>(w_ih, w_hh, b_ih, b_hh, w_fc, b_fc, out);
}